// round 10
// baseline (speedup 1.0000x reference)
#include <cuda_runtime.h>
#include <cuda_fp16.h>
#include <cstdint>

// Problem constants
#define B_   4
#define N_   4096
#define C_   128
#define H_   4
#define D_   32
#define BH_  (B_*H_)           // 16
#define QK_ELEMS (BH_*N_*D_)   // 2,097,152

// ---------------- static scratch (no allocs allowed) ----------------
__device__ __half g_Qh[QK_ELEMS];        // raw q (unnormalized) fp16
__device__ __half g_Kh[QK_ELEMS];        // raw k fp16
__device__ __half g_Vh[QK_ELEMS];
__device__ __half g_Oh[B_*N_*C_];        // attention output fp16 [b][n][h*32+d]
__device__ float  g_part[2][64][512];    // column sumsq partials [q/k][rowchunk][bh*32+d]
__device__ float  g_scale[512];          // 10*log2e / (qnorm*knorm) per (bh,d)

// ---------------- PTX helpers ----------------
#define MMA16816(d, a, b0, b1)                                                  \
    asm volatile("mma.sync.aligned.m16n8k16.row.col.f32.f16.f16.f32 "          \
        "{%0,%1,%2,%3}, {%4,%5,%6,%7}, {%8,%9}, {%0,%1,%2,%3};\n"              \
        : "+f"(d[0]), "+f"(d[1]), "+f"(d[2]), "+f"(d[3])                        \
        : "r"(a[0]), "r"(a[1]), "r"(a[2]), "r"(a[3]), "r"(b0), "r"(b1))

#define LDMX4(r0,r1,r2,r3,addr)                                                 \
    asm volatile("ldmatrix.sync.aligned.m8n8.x4.shared.b16 {%0,%1,%2,%3}, [%4];\n" \
        : "=r"(r0), "=r"(r1), "=r"(r2), "=r"(r3) : "r"(addr))

#define LDMX4T(r0,r1,r2,r3,addr)                                                \
    asm volatile("ldmatrix.sync.aligned.m8n8.x4.trans.shared.b16 {%0,%1,%2,%3}, [%4];\n" \
        : "=r"(r0), "=r"(r1), "=r"(r2), "=r"(r3) : "r"(addr))

__device__ __forceinline__ void cp16(uint32_t dst, const void* src) {
    asm volatile("cp.async.cg.shared.global [%0], [%1], 16;\n" :: "r"(dst), "l"(src));
}
#define CP_COMMIT() asm volatile("cp.async.commit_group;\n" ::: "memory")
#define CP_WAIT0()  asm volatile("cp.async.wait_group 0;\n" ::: "memory")

__device__ __forceinline__ unsigned pack_h2(float x, float y) {
    __half2 h = __float22half2_rn(make_float2(x, y));
    return *reinterpret_cast<unsigned*>(&h);
}
__device__ __forceinline__ unsigned ex2h2(unsigned x) {
    unsigned r; asm("ex2.approx.f16x2 %0, %1;" : "=r"(r) : "r"(x)); return r;
}

// convert two float4 -> int4 of 8 halves
__device__ __forceinline__ int4 cvt8r(float4 v0, float4 v1) {
    __half2 h[4];
    h[0] = __float22half2_rn(make_float2(v0.x, v0.y));
    h[1] = __float22half2_rn(make_float2(v0.z, v0.w));
    h[2] = __float22half2_rn(make_float2(v1.x, v1.y));
    h[3] = __float22half2_rn(make_float2(v1.z, v1.w));
    return *(int4*)h;
}

#define AP 136   // A smem pitch (halves), conflict-free for LDSM
#define BP 72    // B smem pitch (halves)

// =====================================================================
// Kernel 1: QKV GEMM fp16 tensor-core, single-phase K=128, one 64-col
// chunk per block, fused column-sumsq partials for q/k.
// grid (6 nc, 256 mt of 64 rows), 256 thr (8 warps: rowgrp x col-half).
// =====================================================================
__global__ __launch_bounds__(256) void gemm_qkv_h(
    const float* __restrict__ X, const float* __restrict__ Wq)
{
    __shared__ __align__(16) __half As[64][AP];
    __shared__ __align__(16) __half Bs[128][BP];
    __shared__ float wsum[8][64];

    const int nc   = blockIdx.x;      // 0..5
    const int mt   = blockIdx.y;      // 0..255 (64 rows each)
    const int tid  = threadIdx.x;
    const int lane = tid & 31;
    const int warp = tid >> 5;
    const int wr   = (warp & 3) * 16; // row base within tile
    const int wh   = warp >> 2;       // 0/1: 32-col half
    const int g    = lane >> 2;
    const int q2   = (lane & 3) * 2;

    const uint32_t as_base = (uint32_t)__cvta_generic_to_shared(&As[0][0]);
    const uint32_t bs_base = (uint32_t)__cvta_generic_to_shared(&Bs[0][0]);

    // ---- stage A: 64x128 fp32 -> fp16 (32 els/thread) ----
    {
        const int row = tid >> 2;
        const int c0  = (tid & 3) * 32;
        const float* src = X + (mt * 64 + row) * 128 + c0;
        #pragma unroll
        for (int j = 0; j < 4; j++) {
            float4 v0 = *(const float4*)(src + j * 8);
            float4 v1 = *(const float4*)(src + j * 8 + 4);
            *(int4*)&As[row][c0 + j * 8] = cvt8r(v0, v1);
        }
    }
    // ---- stage B: 128x64 fp32 -> fp16 (32 els/thread) ----
    {
        const int brow = tid >> 1;
        const int bc0  = (tid & 1) * 32;
        const float* src = Wq + brow * 384 + nc * 64 + bc0;
        #pragma unroll
        for (int j = 0; j < 4; j++) {
            float4 v0 = *(const float4*)(src + j * 8);
            float4 v1 = *(const float4*)(src + j * 8 + 4);
            *(int4*)&Bs[brow][bc0 + j * 8] = cvt8r(v0, v1);
        }
    }
    __syncthreads();

    // ---- compute 16x32 per warp over K=128 ----
    float acc[4][4];
    #pragma unroll
    for (int t = 0; t < 4; t++)
        #pragma unroll
        for (int r = 0; r < 4; r++) acc[t][r] = 0.f;

    #pragma unroll
    for (int kc = 0; kc < 8; kc++) {
        unsigned a[4];
        LDMX4(a[0], a[1], a[2], a[3], as_base +
            (uint32_t)(((wr + (lane & 15)) * AP + kc * 16 + (lane >> 4) * 8) * 2));
        #pragma unroll
        for (int t = 0; t < 2; t++) {
            unsigned b0, b1, b2, b3;
            LDMX4T(b0, b1, b2, b3, bs_base +
                (uint32_t)(((kc * 16 + (lane & 15)) * BP + wh * 32 + t * 16 + (lane >> 4) * 8) * 2));
            MMA16816(acc[2 * t],     a, b0, b1);
            MMA16816(acc[2 * t + 1], a, b2, b3);
        }
    }

    const int b_batch = mt >> 6;      // batch index
    const int mtc     = mt & 63;      // row-chunk within batch

    // ---- store q/k/v fp16 ----
    #pragma unroll
    for (int t = 0; t < 4; t++) {
        int e  = nc * 64 + wh * 32 + t * 8 + q2;
        int ec = e & 127;
        int h  = ec >> 5, d = ec & 31;
        #pragma unroll
        for (int half_ = 0; half_ < 2; half_++) {
            int m = mt * 64 + wr + g + half_ * 8;
            int n = m & 4095;
            int idx = ((b_batch * 4 + h) * 4096 + n) * 32 + d;
            __half2 hv = __float22half2_rn(
                make_float2(acc[t][half_ * 2], acc[t][half_ * 2 + 1]));
            if (nc < 2)      *(__half2*)&g_Qh[idx] = hv;
            else if (nc < 4) *(__half2*)&g_Kh[idx] = hv;
            else             *(__half2*)&g_Vh[idx] = hv;
        }
    }

    // ---- fused column sumsq partials (q/k only) ----
    if (nc < 4) {
        #pragma unroll
        for (int t = 0; t < 4; t++) {
            float s0 = acc[t][0]*acc[t][0] + acc[t][2]*acc[t][2];
            float s1 = acc[t][1]*acc[t][1] + acc[t][3]*acc[t][3];
            #pragma unroll
            for (int m = 4; m < 32; m <<= 1) {
                s0 += __shfl_xor_sync(0xffffffffu, s0, m);
                s1 += __shfl_xor_sync(0xffffffffu, s1, m);
            }
            if (g == 0) {
                int jloc = wh * 32 + t * 8 + q2;
                wsum[warp][jloc]     = s0;
                wsum[warp][jloc + 1] = s1;
            }
        }
        __syncthreads();
        if (tid < 64) {
            // Column half tid<32 was written only by warps 0-3 (wh=0);
            // half tid>=32 only by warps 4-7 (wh=1). Sum exactly those 4.
            int h4 = tid >> 5;
            float s = wsum[h4 * 4 + 0][tid] + wsum[h4 * 4 + 1][tid]
                    + wsum[h4 * 4 + 2][tid] + wsum[h4 * 4 + 3][tid];
            int e = nc * 64 + tid;
            int which = e >> 7;            // 0=q, 1=k
            int ec = e & 127;
            int h  = ec >> 5, d = ec & 31;
            g_part[which][mtc][(b_batch * 4 + h) * 32 + d] = s;
        }
    }
}

// =====================================================================
// Kernel 2: finalize scale = 10*log2(e)/(qnorm*knorm) -> g_scale[512].
// grid 16 (bh), 256 thr: 8 groups x 32 d, each group 8 chunks.
// =====================================================================
__global__ __launch_bounds__(256) void finalize_scale()
{
    const int bh  = blockIdx.x;
    const int d   = threadIdx.x & 31;
    const int grp = threadIdx.x >> 5;     // 0..7
    float qs = 0.f, ks = 0.f;
    #pragma unroll
    for (int j = 0; j < 8; j++) {
        int c = grp + j * 8;
        qs += g_part[0][c][bh * 32 + d];
        ks += g_part[1][c][bh * 32 + d];
    }
    __shared__ float qred[256], kred[256];
    qred[threadIdx.x] = qs;
    kred[threadIdx.x] = ks;
    __syncthreads();
    if (threadIdx.x < 32) {
        float qt = 0.f, kt = 0.f;
        #pragma unroll
        for (int g = 0; g < 8; g++) {
            qt += qred[g * 32 + d];
            kt += kred[g * 32 + d];
        }
        float qn = fmaxf(sqrtf(qt), 1e-12f);
        float kn = fmaxf(sqrtf(kt), 1e-12f);
        g_scale[bh * 32 + d] = 14.4269504088896f / (qn * kn);  // 10*log2(e)
    }
}

// =====================================================================
// Kernel 3: flash attention. Scale read from g_scale at Q staging;
// exp via ex2.approx.f16x2; row-sum l via ones-MMA; 1 barrier/iter.
// grid (32 q-tiles of 128, 16 bh), 256 thr (8 warps x m16).
// =====================================================================
#define PITCH     40                    // halves per smem row
#define KV_BYTES  (64 * PITCH * 2)      // bytes per K or V stage

__global__ __launch_bounds__(256) void flash_kernel()
{
    const int qt   = blockIdx.x;      // 0..31
    const int bh   = blockIdx.y;      // 0..15
    const int tid  = threadIdx.x;
    const int lane = tid & 31;
    const int warp = tid >> 5;        // 0..7
    const int g    = lane >> 2;       // 0..7

    __shared__ __align__(16) __half Qs[128][PITCH];
    __shared__ __align__(16) __half Ks[2][64][PITCH];
    __shared__ __align__(16) __half Vs[2][64][PITCH];

    const __half* Qg = g_Qh + (bh * N_ + qt * 128) * 32;
    const __half* Kg = g_Kh + bh * N_ * 32;
    const __half* Vg = g_Vh + bh * N_ * 32;

    const uint32_t qs_base = (uint32_t)__cvta_generic_to_shared(&Qs[0][0]);
    const uint32_t ks_base = (uint32_t)__cvta_generic_to_shared(&Ks[0][0][0]);
    const uint32_t vs_base = (uint32_t)__cvta_generic_to_shared(&Vs[0][0][0]);

    const int crow = tid >> 2;
    const int ccol = (tid & 3) * 8;
    const uint32_t cdst = (uint32_t)(crow * (PITCH * 2) + ccol * 2);
    const int     csrc  = crow * 32 + ccol;

    // prefetch KV tile 0
    cp16(ks_base + cdst, Kg + csrc);
    cp16(vs_base + cdst, Vg + csrc);
    CP_COMMIT();

    // stage Q (raw fp16 * fp32 scale -> fp16) while tile 0 streams
    {
        const int d0 = (tid & 3) * 8;
        float sc[8];
        #pragma unroll
        for (int j = 0; j < 8; j++) sc[j] = g_scale[bh * 32 + d0 + j];
        const int4* src = (const int4*)Qg;
        #pragma unroll
        for (int i = tid; i < 512; i += 256) {
            int4 v = src[i];
            __half2* hp = (__half2*)&v;
            #pragma unroll
            for (int j = 0; j < 4; j++) {
                float2 fv = __half22float2(hp[j]);
                fv.x *= sc[2 * j]; fv.y *= sc[2 * j + 1];
                hp[j] = __float22half2_rn(fv);
            }
            *(int4*)&Qs[i >> 2][(i & 3) * 8] = v;
        }
    }
    __syncthreads();

    // Q A-fragments for the whole loop
    unsigned qa[2][4];
    const int rb = warp * 16;
    #pragma unroll
    for (int kc = 0; kc < 2; kc++) {
        uint32_t addr = qs_base +
            (uint32_t)(((rb + (lane & 15)) * PITCH + kc * 16 + (lane >> 4) * 8) * 2);
        LDMX4(qa[kc][0], qa[kc][1], qa[kc][2], qa[kc][3], addr);
    }

    float o[4][4];
    #pragma unroll
    for (int t = 0; t < 4; t++)
        #pragma unroll
        for (int r = 0; r < 4; r++) o[t][r] = 0.f;
    float lacc[4] = {0.f, 0.f, 0.f, 0.f};
    const unsigned ONES = 0x3C003C00u;    // (1.0h, 1.0h)

    for (int kb = 0; kb < 64; kb++) {
        const int st = kb & 1;
        CP_WAIT0();
        __syncthreads();

        if (kb + 1 < 64) {     // prefetch next tile, overlaps compute
            uint32_t off = (uint32_t)((st ^ 1) * KV_BYTES) + cdst;
            int s2 = (kb + 1) * 64 * 32 + csrc;
            cp16(ks_base + off, Kg + s2);
            cp16(vs_base + off, Vg + s2);
            CP_COMMIT();
        }

        const uint32_t kbase = ks_base + st * KV_BYTES;
        const uint32_t vbase = vs_base + st * KV_BYTES;

        // ---- S = Q K^T (16 x 64 per warp), log2-domain logits ----
        float s[8][4];
        #pragma unroll
        for (int t = 0; t < 8; t++) {
            unsigned b0, b1, b2, b3;
            uint32_t addr = kbase +
                (uint32_t)(((t * 8 + (lane & 7)) * PITCH + (lane >> 3) * 8) * 2);
            LDMX4(b0, b1, b2, b3, addr);
            s[t][0] = s[t][1] = s[t][2] = s[t][3] = 0.f;
            MMA16816(s[t], qa[0], b0, b1);
            MMA16816(s[t], qa[1], b2, b3);
        }

        // ---- per jc-chunk: pack -> ex2.f16x2 -> l-MMA + PV MMAs ----
        #pragma unroll
        for (int jc = 0; jc < 4; jc++) {
            unsigned pu[4];
            pu[0] = ex2h2(pack_h2(s[2*jc][0],   s[2*jc][1]));
            pu[1] = ex2h2(pack_h2(s[2*jc][2],   s[2*jc][3]));
            pu[2] = ex2h2(pack_h2(s[2*jc+1][0], s[2*jc+1][1]));
            pu[3] = ex2h2(pack_h2(s[2*jc+1][2], s[2*jc+1][3]));

            MMA16816(lacc, pu, ONES, ONES);   // row sums -> persistent fp32 acc

            uint32_t a0 = vbase +
                (uint32_t)(((jc * 16 + (lane & 15)) * PITCH + (lane >> 4) * 8) * 2);
            unsigned r0, r1, r2, r3;
            LDMX4T(r0, r1, r2, r3, a0);
            MMA16816(o[0], pu, r0, r1);
            MMA16816(o[1], pu, r2, r3);
            LDMX4T(r0, r1, r2, r3, a0 + 32);
            MMA16816(o[2], pu, r0, r1);
            MMA16816(o[3], pu, r2, r3);
        }
    }

    // ---- finalize: l broadcast across accumulator columns ----
    const int q2 = (lane & 3) * 2;
    float inv0 = 1.0f / lacc[0];
    float inv1 = 1.0f / lacc[2];

    int b = bh >> 2, h = bh & 3;
    int row0 = qt * 128 + rb + g;
    __half* dst0 = g_Oh + (b * N_ + row0) * 128 + h * 32;
    __half* dst1 = dst0 + 8 * 128;
    #pragma unroll
    for (int t = 0; t < 4; t++) {
        int d = t * 8 + q2;
        *(__half2*)&dst0[d] = __float22half2_rn(make_float2(o[t][0] * inv0, o[t][1] * inv0));
        *(__half2*)&dst1[d] = __float22half2_rn(make_float2(o[t][2] * inv1, o[t][3] * inv1));
    }
}

// =====================================================================
// Kernel 4: output projection, single-pass K=128, 64x64 tiles.
// grid (2 nc, 256 mt), 256 thr (8 warps: rowgrp x 32-col half).
// =====================================================================
__global__ __launch_bounds__(256) void gemm_out_h(
    const float* __restrict__ Wo, const float* __restrict__ bias,
    float* __restrict__ out)
{
    __shared__ __align__(16) __half As[64][AP];
    __shared__ __align__(16) __half Bs[128][BP];

    const int nc   = blockIdx.x;      // 0..1
    const int mt   = blockIdx.y;      // 0..255
    const int tid  = threadIdx.x;
    const int lane = tid & 31;
    const int warp = tid >> 5;
    const int wr   = (warp & 3) * 16;
    const int wh   = warp >> 2;
    const int g    = lane >> 2;
    const int q2   = (lane & 3) * 2;

    const uint32_t as_base = (uint32_t)__cvta_generic_to_shared(&As[0][0]);
    const uint32_t bs_base = (uint32_t)__cvta_generic_to_shared(&Bs[0][0]);
    const __half* Ap = g_Oh + mt * 64 * 128;

    // A: 64x128 fp16 via cp.async (1024 16B chunks, 4/thread)
    #pragma unroll
    for (int j = 0; j < 4; j++) {
        int i = tid + j * 256;
        int row = i >> 4, c8 = (i & 15) * 8;
        cp16(as_base + (uint32_t)((row * AP + c8) * 2), Ap + row * 128 + c8);
    }
    CP_COMMIT();

    // B: 128x64 fp32 -> fp16 (32 els/thread)
    {
        const int brow = tid >> 1;
        const int bc0  = (tid & 1) * 32;
        const float* src = Wo + brow * 128 + nc * 64 + bc0;
        #pragma unroll
        for (int j = 0; j < 4; j++) {
            float4 v0 = *(const float4*)(src + j * 8);
            float4 v1 = *(const float4*)(src + j * 8 + 4);
            *(int4*)&Bs[brow][bc0 + j * 8] = cvt8r(v0, v1);
        }
    }
    CP_WAIT0();
    __syncthreads();

    float acc[4][4];
    #pragma unroll
    for (int t = 0; t < 4; t++)
        #pragma unroll
        for (int r = 0; r < 4; r++) acc[t][r] = 0.f;

    #pragma unroll
    for (int kc = 0; kc < 8; kc++) {
        unsigned a[4];
        LDMX4(a[0], a[1], a[2], a[3], as_base +
            (uint32_t)(((wr + (lane & 15)) * AP + kc * 16 + (lane >> 4) * 8) * 2));
        #pragma unroll
        for (int t = 0; t < 2; t++) {
            unsigned b0, b1, b2, b3;
            LDMX4T(b0, b1, b2, b3, bs_base +
                (uint32_t)(((kc * 16 + (lane & 15)) * BP + wh * 32 + t * 16 + (lane >> 4) * 8) * 2));
            MMA16816(acc[2 * t],     a, b0, b1);
            MMA16816(acc[2 * t + 1], a, b2, b3);
        }
    }

    #pragma unroll
    for (int t = 0; t < 4; t++) {
        int e = nc * 64 + wh * 32 + t * 8 + q2;
        float2 bv = *(const float2*)&bias[e];
        #pragma unroll
        for (int half_ = 0; half_ < 2; half_++) {
            int m = mt * 64 + wr + g + half_ * 8;
            *(float2*)&out[m * 128 + e] =
                make_float2(acc[t][half_ * 2] + bv.x, acc[t][half_ * 2 + 1] + bv.y);
        }
    }
}

// =====================================================================
extern "C" void kernel_launch(void* const* d_in, const int* in_sizes, int n_in,
                              void* d_out, int out_size)
{
    const float* x     = (const float*)d_in[0];   // [4,4096,128]
    const float* Wqkv  = (const float*)d_in[1];   // [128,384]
    const float* Wout  = (const float*)d_in[2];   // [128,128]
    const float* bout  = (const float*)d_in[3];   // [128]
    float* out = (float*)d_out;                   // [4,4096,128]

    gemm_qkv_h<<<dim3(6, 256), 256>>>(x, Wqkv);
    finalize_scale<<<16, 256>>>();
    flash_kernel<<<dim3(32, 16), 256>>>();
    gemm_out_h<<<dim3(2, 256), 256>>>(Wout, bout, out);
}

// round 11
// speedup vs baseline: 1.0995x; 1.0995x over previous
#include <cuda_runtime.h>
#include <cuda_fp16.h>
#include <cstdint>

// Problem constants
#define B_   4
#define N_   4096
#define C_   128
#define H_   4
#define D_   32
#define BH_  (B_*H_)           // 16
#define QK_ELEMS (BH_*N_*D_)   // 2,097,152

// ---------------- static scratch (no allocs allowed) ----------------
__device__ __half g_Qh[QK_ELEMS];        // raw q (unnormalized) fp16
__device__ __half g_Kh[QK_ELEMS];        // raw k fp16
__device__ __half g_Vh[QK_ELEMS];
__device__ __half g_Oh[B_*N_*C_];        // attention output fp16 [b][n][h*32+d]
__device__ float  g_part[2][64][512];    // column sumsq partials [q/k][rowchunk][bh*32+d]
__device__ float  g_scale[512];          // 10*log2e / (qnorm*knorm) per (bh,d)

// ---------------- PTX helpers ----------------
#define MMA16816(d, a, b0, b1)                                                  \
    asm volatile("mma.sync.aligned.m16n8k16.row.col.f32.f16.f16.f32 "          \
        "{%0,%1,%2,%3}, {%4,%5,%6,%7}, {%8,%9}, {%0,%1,%2,%3};\n"              \
        : "+f"(d[0]), "+f"(d[1]), "+f"(d[2]), "+f"(d[3])                        \
        : "r"(a[0]), "r"(a[1]), "r"(a[2]), "r"(a[3]), "r"(b0), "r"(b1))

#define LDMX4(r0,r1,r2,r3,addr)                                                 \
    asm volatile("ldmatrix.sync.aligned.m8n8.x4.shared.b16 {%0,%1,%2,%3}, [%4];\n" \
        : "=r"(r0), "=r"(r1), "=r"(r2), "=r"(r3) : "r"(addr))

#define LDMX4T(r0,r1,r2,r3,addr)                                                \
    asm volatile("ldmatrix.sync.aligned.m8n8.x4.trans.shared.b16 {%0,%1,%2,%3}, [%4];\n" \
        : "=r"(r0), "=r"(r1), "=r"(r2), "=r"(r3) : "r"(addr))

__device__ __forceinline__ void cp16(uint32_t dst, const void* src) {
    asm volatile("cp.async.cg.shared.global [%0], [%1], 16;\n" :: "r"(dst), "l"(src));
}
#define CP_COMMIT() asm volatile("cp.async.commit_group;\n" ::: "memory")
#define CP_WAIT0()  asm volatile("cp.async.wait_group 0;\n" ::: "memory")

__device__ __forceinline__ unsigned pack_h2(float x, float y) {
    __half2 h = __float22half2_rn(make_float2(x, y));
    return *reinterpret_cast<unsigned*>(&h);
}
__device__ __forceinline__ unsigned ex2h2(unsigned x) {
    unsigned r; asm("ex2.approx.f16x2 %0, %1;" : "=r"(r) : "r"(x)); return r;
}

// convert two float4 -> int4 of 8 halves
__device__ __forceinline__ int4 cvt8r(float4 v0, float4 v1) {
    __half2 h[4];
    h[0] = __float22half2_rn(make_float2(v0.x, v0.y));
    h[1] = __float22half2_rn(make_float2(v0.z, v0.w));
    h[2] = __float22half2_rn(make_float2(v1.x, v1.y));
    h[3] = __float22half2_rn(make_float2(v1.z, v1.w));
    return *(int4*)h;
}

#define AP 136   // A smem pitch (halves), conflict-free for LDSM
#define BP 72    // B smem pitch (halves)
#define GP 72    // pitch for gemm_out two-phase tiles

// =====================================================================
// Kernel 1 (round-8 measured 31us): QKV GEMM fp16 tensor-core with
// A-tile staged ONCE and reused across all 384 output columns +
// fused column-sumsq partials for q/k. Block: 64 rows x 384 cols.
// grid 256, 256 thr (8 warps: (w&3)=rowgrp, (w>>2)=32-col half).
// =====================================================================
__global__ __launch_bounds__(256) void gemm_qkv_h(
    const float* __restrict__ X, const float* __restrict__ Wq)
{
    __shared__ __align__(16) __half As[64][AP];
    __shared__ __align__(16) __half Bs[128][BP];
    __shared__ float wsum[8][64];

    const int mt   = blockIdx.x;      // 0..255 (64 rows each)
    const int tid  = threadIdx.x;
    const int lane = tid & 31;
    const int warp = tid >> 5;
    const int wr   = (warp & 3) * 16; // row base within tile
    const int wh   = warp >> 2;       // 0/1: 32-col half
    const int g    = lane >> 2;
    const int q2   = (lane & 3) * 2;

    const uint32_t as_base = (uint32_t)__cvta_generic_to_shared(&As[0][0]);
    const uint32_t bs_base = (uint32_t)__cvta_generic_to_shared(&Bs[0][0]);

    // ---- stage A once: 64x128 fp32 -> fp16 smem ----
    {
        const int row = tid >> 2;
        const int c0  = (tid & 3) * 32;
        const float* src = X + (mt * 64 + row) * 128 + c0;
        #pragma unroll
        for (int j = 0; j < 4; j++) {
            float4 v0 = *(const float4*)(src + j * 8);
            float4 v1 = *(const float4*)(src + j * 8 + 4);
            *(int4*)&As[row][c0 + j * 8] = cvt8r(v0, v1);
        }
    }

    // ---- B prefetch registers (128x64 fp32 per nc; 32 els/thread) ----
    const int brow = tid >> 1;
    const int bc0  = (tid & 1) * 32;
    float4 f[8];
    {
        const float* src = Wq + brow * 384 + 0 * 64 + bc0;
        #pragma unroll
        for (int j = 0; j < 4; j++) {
            f[2*j]   = *(const float4*)(src + j * 8);
            f[2*j+1] = *(const float4*)(src + j * 8 + 4);
        }
    }

    const int b_batch = mt >> 6;      // batch index
    const int mtc     = mt & 63;      // row-chunk within batch (for g_part)

    #pragma unroll 1
    for (int nc = 0; nc < 6; nc++) {
        // store B(nc) to smem
        #pragma unroll
        for (int j = 0; j < 4; j++)
            *(int4*)&Bs[brow][bc0 + j * 8] = cvt8r(f[2*j], f[2*j+1]);
        __syncthreads();

        // prefetch B(nc+1)
        if (nc < 5) {
            const float* src = Wq + brow * 384 + (nc + 1) * 64 + bc0;
            #pragma unroll
            for (int j = 0; j < 4; j++) {
                f[2*j]   = *(const float4*)(src + j * 8);
                f[2*j+1] = *(const float4*)(src + j * 8 + 4);
            }
        }

        // ---- compute 16x32 per warp over K=128 ----
        float acc[4][4];
        #pragma unroll
        for (int t = 0; t < 4; t++)
            #pragma unroll
            for (int r = 0; r < 4; r++) acc[t][r] = 0.f;

        #pragma unroll
        for (int kc = 0; kc < 8; kc++) {
            unsigned a[4];
            LDMX4(a[0], a[1], a[2], a[3], as_base +
                (uint32_t)(((wr + (lane & 15)) * AP + kc * 16 + (lane >> 4) * 8) * 2));
            #pragma unroll
            for (int t = 0; t < 2; t++) {
                unsigned b0, b1, b2, b3;
                LDMX4T(b0, b1, b2, b3, bs_base +
                    (uint32_t)(((kc * 16 + (lane & 15)) * BP + wh * 32 + t * 16 + (lane >> 4) * 8) * 2));
                MMA16816(acc[2 * t],     a, b0, b1);
                MMA16816(acc[2 * t + 1], a, b2, b3);
            }
        }

        // ---- store q/k/v fp16 ----
        #pragma unroll
        for (int t = 0; t < 4; t++) {
            int e  = nc * 64 + wh * 32 + t * 8 + q2;
            int ec = e & 127;
            int h  = ec >> 5, d = ec & 31;
            #pragma unroll
            for (int half_ = 0; half_ < 2; half_++) {
                int m = mt * 64 + wr + g + half_ * 8;
                int n = m & 4095;
                int idx = ((b_batch * 4 + h) * 4096 + n) * 32 + d;
                __half2 hv = __float22half2_rn(
                    make_float2(acc[t][half_ * 2], acc[t][half_ * 2 + 1]));
                if (nc < 2)      *(__half2*)&g_Qh[idx] = hv;
                else if (nc < 4) *(__half2*)&g_Kh[idx] = hv;
                else             *(__half2*)&g_Vh[idx] = hv;
            }
        }

        // ---- fused column sumsq partials (q/k only) ----
        if (nc < 4) {
            #pragma unroll
            for (int t = 0; t < 4; t++) {
                float s0 = acc[t][0]*acc[t][0] + acc[t][2]*acc[t][2];
                float s1 = acc[t][1]*acc[t][1] + acc[t][3]*acc[t][3];
                #pragma unroll
                for (int m = 4; m < 32; m <<= 1) {
                    s0 += __shfl_xor_sync(0xffffffffu, s0, m);
                    s1 += __shfl_xor_sync(0xffffffffu, s1, m);
                }
                if (g == 0) {
                    int jloc = wh * 32 + t * 8 + q2;
                    wsum[warp][jloc]     = s0;
                    wsum[warp][jloc + 1] = s1;
                }
            }
        }
        __syncthreads();   // compute + wsum done; Bs free for next STS

        if (nc < 4 && tid < 64) {
            // col half tid<32 written by warps 0-3 (wh=0); tid>=32 by 4-7.
            int h4 = tid >> 5;
            float s = wsum[h4*4+0][tid] + wsum[h4*4+1][tid]
                    + wsum[h4*4+2][tid] + wsum[h4*4+3][tid];
            int e = nc * 64 + tid;
            int which = e >> 7;            // 0=q, 1=k
            int ec = e & 127;
            int h  = ec >> 5, d = ec & 31;
            g_part[which][mtc][(b_batch * 4 + h) * 32 + d] = s;
        }
    }
}

// =====================================================================
// Kernel 2: finalize scale = 10*log2(e)/(qnorm*knorm) -> g_scale[512].
// grid 16 (bh), 256 thr: 8 groups x 32 d, each group 8 chunks.
// =====================================================================
__global__ __launch_bounds__(256) void finalize_scale()
{
    const int bh  = blockIdx.x;
    const int d   = threadIdx.x & 31;
    const int grp = threadIdx.x >> 5;     // 0..7
    float qs = 0.f, ks = 0.f;
    #pragma unroll
    for (int j = 0; j < 8; j++) {
        int c = grp + j * 8;
        qs += g_part[0][c][bh * 32 + d];
        ks += g_part[1][c][bh * 32 + d];
    }
    __shared__ float qred[256], kred[256];
    qred[threadIdx.x] = qs;
    kred[threadIdx.x] = ks;
    __syncthreads();
    if (threadIdx.x < 32) {
        float qt = 0.f, kt = 0.f;
        #pragma unroll
        for (int g = 0; g < 8; g++) {
            qt += qred[g * 32 + d];
            kt += kred[g * 32 + d];
        }
        float qn = fmaxf(sqrtf(qt), 1e-12f);
        float kn = fmaxf(sqrtf(kt), 1e-12f);
        g_scale[bh * 32 + d] = 14.4269504088896f / (qn * kn);  // 10*log2(e)
    }
}

// =====================================================================
// Kernel 3: flash attention. Scale read from g_scale at Q staging;
// exp via ex2.approx.f16x2; row-sum l via ones-MMA; 1 barrier/iter.
// grid (32 q-tiles of 128, 16 bh), 256 thr (8 warps x m16).
// =====================================================================
#define PITCH     40                    // halves per smem row
#define KV_BYTES  (64 * PITCH * 2)      // bytes per K or V stage

__global__ __launch_bounds__(256) void flash_kernel()
{
    const int qt   = blockIdx.x;      // 0..31
    const int bh   = blockIdx.y;      // 0..15
    const int tid  = threadIdx.x;
    const int lane = tid & 31;
    const int warp = tid >> 5;        // 0..7
    const int g    = lane >> 2;       // 0..7

    __shared__ __align__(16) __half Qs[128][PITCH];
    __shared__ __align__(16) __half Ks[2][64][PITCH];
    __shared__ __align__(16) __half Vs[2][64][PITCH];

    const __half* Qg = g_Qh + (bh * N_ + qt * 128) * 32;
    const __half* Kg = g_Kh + bh * N_ * 32;
    const __half* Vg = g_Vh + bh * N_ * 32;

    const uint32_t qs_base = (uint32_t)__cvta_generic_to_shared(&Qs[0][0]);
    const uint32_t ks_base = (uint32_t)__cvta_generic_to_shared(&Ks[0][0][0]);
    const uint32_t vs_base = (uint32_t)__cvta_generic_to_shared(&Vs[0][0][0]);

    const int crow = tid >> 2;
    const int ccol = (tid & 3) * 8;
    const uint32_t cdst = (uint32_t)(crow * (PITCH * 2) + ccol * 2);
    const int     csrc  = crow * 32 + ccol;

    // prefetch KV tile 0
    cp16(ks_base + cdst, Kg + csrc);
    cp16(vs_base + cdst, Vg + csrc);
    CP_COMMIT();

    // stage Q (raw fp16 * fp32 scale -> fp16) while tile 0 streams
    {
        const int d0 = (tid & 3) * 8;
        float sc[8];
        #pragma unroll
        for (int j = 0; j < 8; j++) sc[j] = g_scale[bh * 32 + d0 + j];
        const int4* src = (const int4*)Qg;
        #pragma unroll
        for (int i = tid; i < 512; i += 256) {
            int4 v = src[i];
            __half2* hp = (__half2*)&v;
            #pragma unroll
            for (int j = 0; j < 4; j++) {
                float2 fv = __half22float2(hp[j]);
                fv.x *= sc[2 * j]; fv.y *= sc[2 * j + 1];
                hp[j] = __float22half2_rn(fv);
            }
            *(int4*)&Qs[i >> 2][(i & 3) * 8] = v;
        }
    }
    __syncthreads();

    // Q A-fragments for the whole loop
    unsigned qa[2][4];
    const int rb = warp * 16;
    #pragma unroll
    for (int kc = 0; kc < 2; kc++) {
        uint32_t addr = qs_base +
            (uint32_t)(((rb + (lane & 15)) * PITCH + kc * 16 + (lane >> 4) * 8) * 2);
        LDMX4(qa[kc][0], qa[kc][1], qa[kc][2], qa[kc][3], addr);
    }

    float o[4][4];
    #pragma unroll
    for (int t = 0; t < 4; t++)
        #pragma unroll
        for (int r = 0; r < 4; r++) o[t][r] = 0.f;
    float lacc[4] = {0.f, 0.f, 0.f, 0.f};
    const unsigned ONES = 0x3C003C00u;    // (1.0h, 1.0h)

    for (int kb = 0; kb < 64; kb++) {
        const int st = kb & 1;
        CP_WAIT0();
        __syncthreads();

        if (kb + 1 < 64) {     // prefetch next tile, overlaps compute
            uint32_t off = (uint32_t)((st ^ 1) * KV_BYTES) + cdst;
            int s2 = (kb + 1) * 64 * 32 + csrc;
            cp16(ks_base + off, Kg + s2);
            cp16(vs_base + off, Vg + s2);
            CP_COMMIT();
        }

        const uint32_t kbase = ks_base + st * KV_BYTES;
        const uint32_t vbase = vs_base + st * KV_BYTES;

        // ---- S = Q K^T (16 x 64 per warp), log2-domain logits ----
        float s[8][4];
        #pragma unroll
        for (int t = 0; t < 8; t++) {
            unsigned b0, b1, b2, b3;
            uint32_t addr = kbase +
                (uint32_t)(((t * 8 + (lane & 7)) * PITCH + (lane >> 3) * 8) * 2);
            LDMX4(b0, b1, b2, b3, addr);
            s[t][0] = s[t][1] = s[t][2] = s[t][3] = 0.f;
            MMA16816(s[t], qa[0], b0, b1);
            MMA16816(s[t], qa[1], b2, b3);
        }

        // ---- per jc-chunk: pack -> ex2.f16x2 -> l-MMA + PV MMAs ----
        #pragma unroll
        for (int jc = 0; jc < 4; jc++) {
            unsigned pu[4];
            pu[0] = ex2h2(pack_h2(s[2*jc][0],   s[2*jc][1]));
            pu[1] = ex2h2(pack_h2(s[2*jc][2],   s[2*jc][3]));
            pu[2] = ex2h2(pack_h2(s[2*jc+1][0], s[2*jc+1][1]));
            pu[3] = ex2h2(pack_h2(s[2*jc+1][2], s[2*jc+1][3]));

            MMA16816(lacc, pu, ONES, ONES);   // row sums -> persistent fp32 acc

            uint32_t a0 = vbase +
                (uint32_t)(((jc * 16 + (lane & 15)) * PITCH + (lane >> 4) * 8) * 2);
            unsigned r0, r1, r2, r3;
            LDMX4T(r0, r1, r2, r3, a0);
            MMA16816(o[0], pu, r0, r1);
            MMA16816(o[1], pu, r2, r3);
            LDMX4T(r0, r1, r2, r3, a0 + 32);
            MMA16816(o[2], pu, r0, r1);
            MMA16816(o[3], pu, r2, r3);
        }
    }

    // ---- finalize: l broadcast across accumulator columns ----
    const int q2 = (lane & 3) * 2;
    float inv0 = 1.0f / lacc[0];
    float inv1 = 1.0f / lacc[2];

    int b = bh >> 2, h = bh & 3;
    int row0 = qt * 128 + rb + g;
    __half* dst0 = g_Oh + (b * N_ + row0) * 128 + h * 32;
    __half* dst1 = dst0 + 8 * 128;
    #pragma unroll
    for (int t = 0; t < 4; t++) {
        int d = t * 8 + q2;
        *(__half2*)&dst0[d] = __float22half2_rn(make_float2(o[t][0] * inv0, o[t][1] * inv0));
        *(__half2*)&dst1[d] = __float22half2_rn(make_float2(o[t][2] * inv1, o[t][3] * inv1));
    }
}

// =====================================================================
// Kernel 4 (round-7 measured 8.3us): output projection, two-phase
// K=128, 128x64 tiles. grid (2 nc, 128 mt), 256 thr (8 warps x 16 rows).
// =====================================================================
__global__ __launch_bounds__(256) void gemm_out_h(
    const float* __restrict__ Wo, const float* __restrict__ bias,
    float* __restrict__ out)
{
    __shared__ __align__(16) __half As[128][GP];
    __shared__ __align__(16) __half Bs[64][GP];
    const int nc  = blockIdx.x;       // 0..1
    const int mt  = blockIdx.y;       // 0..127
    const int tid = threadIdx.x;
    const int lane = tid & 31;
    const int warp = tid >> 5;
    const int g    = lane >> 2;
    const int q2   = (lane & 3) * 2;

    const uint32_t as_base = (uint32_t)__cvta_generic_to_shared(&As[0][0]);
    const uint32_t bs_base = (uint32_t)__cvta_generic_to_shared(&Bs[0][0]);
    const __half* Ap = g_Oh + mt * 128 * 128;

    float acc[8][4];
    #pragma unroll
    for (int t = 0; t < 8; t++)
        #pragma unroll
        for (int r = 0; r < 4; r++) acc[t][r] = 0.f;

    #pragma unroll
    for (int p = 0; p < 2; p++) {
        if (p) __syncthreads();
        #pragma unroll
        for (int j = 0; j < 4; j++) {        // A: fp16 via cp.async
            int i = tid + j * 256;
            int row = i >> 3, c8 = (i & 7) * 8;
            cp16(as_base + (uint32_t)((row * GP + c8) * 2),
                 Ap + row * 128 + p * 64 + c8);
        }
        #pragma unroll
        for (int j = 0; j < 2; j++) {        // B: fp32 -> fp16 in staging
            int i = tid + j * 256;
            int row = i >> 3, c8 = (i & 7) * 8;
            const float* src = Wo + (p * 64 + row) * 128 + nc * 64 + c8;
            float4 v0 = *(const float4*)src;
            float4 v1 = *(const float4*)(src + 4);
            *(int4*)&Bs[row][c8] = cvt8r(v0, v1);
        }
        CP_COMMIT(); CP_WAIT0();
        __syncthreads();

        #pragma unroll
        for (int kc = 0; kc < 4; kc++) {
            unsigned a[4];
            LDMX4(a[0], a[1], a[2], a[3], as_base +
                (uint32_t)(((warp * 16 + (lane & 15)) * GP + kc * 16 + (lane >> 4) * 8) * 2));
            #pragma unroll
            for (int t = 0; t < 4; t++) {
                unsigned b0, b1, b2, b3;
                LDMX4T(b0, b1, b2, b3, bs_base +
                    (uint32_t)(((kc * 16 + (lane & 15)) * GP + t * 16 + (lane >> 4) * 8) * 2));
                MMA16816(acc[2 * t],     a, b0, b1);
                MMA16816(acc[2 * t + 1], a, b2, b3);
            }
        }
    }

    #pragma unroll
    for (int t = 0; t < 8; t++) {
        int e = nc * 64 + t * 8 + q2;
        float2 bv = *(const float2*)&bias[e];
        #pragma unroll
        for (int half_ = 0; half_ < 2; half_++) {
            int m = mt * 128 + warp * 16 + g + half_ * 8;
            *(float2*)&out[m * 128 + e] =
                make_float2(acc[t][half_ * 2] + bv.x, acc[t][half_ * 2 + 1] + bv.y);
        }
    }
}

// =====================================================================
extern "C" void kernel_launch(void* const* d_in, const int* in_sizes, int n_in,
                              void* d_out, int out_size)
{
    const float* x     = (const float*)d_in[0];   // [4,4096,128]
    const float* Wqkv  = (const float*)d_in[1];   // [128,384]
    const float* Wout  = (const float*)d_in[2];   // [128,128]
    const float* bout  = (const float*)d_in[3];   // [128]
    float* out = (float*)d_out;                   // [4,4096,128]

    gemm_qkv_h<<<256, 256>>>(x, Wqkv);
    finalize_scale<<<16, 256>>>();
    flash_kernel<<<dim3(32, 16), 256>>>();
    gemm_out_h<<<dim3(2, 128), 256>>>(Wout, bout, out);
}

// round 12
// speedup vs baseline: 1.1872x; 1.0798x over previous
#include <cuda_runtime.h>
#include <cuda_fp16.h>
#include <cstdint>

// Problem constants
#define B_   4
#define N_   4096
#define C_   128
#define H_   4
#define D_   32
#define BH_  (B_*H_)           // 16
#define QK_ELEMS (BH_*N_*D_)   // 2,097,152

// ---------------- static scratch (no allocs allowed) ----------------
__device__ __half g_Qh[QK_ELEMS];        // raw q (unnormalized) fp16
__device__ __half g_Kh[QK_ELEMS];        // raw k fp16
__device__ __half g_Vh[QK_ELEMS];
__device__ __half g_Oh[B_*N_*C_];        // attention output fp16 [b][n][h*32+d]
__device__ float  g_part[2][8][512];     // column sumsq partials [q/k][chunk][bh*32+d]

// ---------------- PTX helpers ----------------
#define MMA16816(d, a, b0, b1)                                                  \
    asm volatile("mma.sync.aligned.m16n8k16.row.col.f32.f16.f16.f32 "          \
        "{%0,%1,%2,%3}, {%4,%5,%6,%7}, {%8,%9}, {%0,%1,%2,%3};\n"              \
        : "+f"(d[0]), "+f"(d[1]), "+f"(d[2]), "+f"(d[3])                        \
        : "r"(a[0]), "r"(a[1]), "r"(a[2]), "r"(a[3]), "r"(b0), "r"(b1))

#define LDMX4(r0,r1,r2,r3,addr)                                                 \
    asm volatile("ldmatrix.sync.aligned.m8n8.x4.shared.b16 {%0,%1,%2,%3}, [%4];\n" \
        : "=r"(r0), "=r"(r1), "=r"(r2), "=r"(r3) : "r"(addr))

#define LDMX4T(r0,r1,r2,r3,addr)                                                \
    asm volatile("ldmatrix.sync.aligned.m8n8.x4.trans.shared.b16 {%0,%1,%2,%3}, [%4];\n" \
        : "=r"(r0), "=r"(r1), "=r"(r2), "=r"(r3) : "r"(addr))

__device__ __forceinline__ void cp16(uint32_t dst, const void* src) {
    asm volatile("cp.async.cg.shared.global [%0], [%1], 16;\n" :: "r"(dst), "l"(src));
}
#define CP_COMMIT() asm volatile("cp.async.commit_group;\n" ::: "memory")
#define CP_WAIT0()  asm volatile("cp.async.wait_group 0;\n" ::: "memory")

__device__ __forceinline__ unsigned pack_h2(float x, float y) {
    __half2 h = __float22half2_rn(make_float2(x, y));
    return *reinterpret_cast<unsigned*>(&h);
}
__device__ __forceinline__ unsigned ex2h2(unsigned x) {
    unsigned r; asm("ex2.approx.f16x2 %0, %1;" : "=r"(r) : "r"(x)); return r;
}
__device__ __forceinline__ __half2 u2h2(unsigned x) {
    return *reinterpret_cast<__half2*>(&x);
}

// convert 8 consecutive fp32 -> int4 of 8 halves
__device__ __forceinline__ int4 cvt8(const float* __restrict__ src) {
    float4 v0 = *(const float4*)src;
    float4 v1 = *(const float4*)(src + 4);
    __half2 h[4];
    h[0] = __float22half2_rn(make_float2(v0.x, v0.y));
    h[1] = __float22half2_rn(make_float2(v0.z, v0.w));
    h[2] = __float22half2_rn(make_float2(v1.x, v1.y));
    h[3] = __float22half2_rn(make_float2(v1.z, v1.w));
    return *(int4*)h;
}

// =====================================================================
// Kernel 1: QKV GEMM fp16 tensor-core, fp32 inputs converted in-staging.
// (X[16384,128]fp32 @ Wqkv[128,384]fp32), fp32 acc, q/k/v fp16 out
// in [bh][n][d] layout. grid (6 nc of 64, 128 mt of 128), 256 thr.
// =====================================================================
#define GP 72   // smem pitch in halves

__global__ __launch_bounds__(256) void gemm_qkv_h(
    const float* __restrict__ X, const float* __restrict__ Wq)
{
    __shared__ __align__(16) __half As[128][GP];
    __shared__ __align__(16) __half Bs[64][GP];
    const int nc  = blockIdx.x;       // 0..5
    const int mt  = blockIdx.y;       // 0..127
    const int tid = threadIdx.x;
    const int lane = tid & 31;
    const int warp = tid >> 5;
    const int g    = lane >> 2;
    const int q2   = (lane & 3) * 2;

    const uint32_t as_base = (uint32_t)__cvta_generic_to_shared(&As[0][0]);
    const uint32_t bs_base = (uint32_t)__cvta_generic_to_shared(&Bs[0][0]);

    float acc[8][4];
    #pragma unroll
    for (int t = 0; t < 8; t++)
        #pragma unroll
        for (int r = 0; r < 4; r++) acc[t][r] = 0.f;

    #pragma unroll
    for (int p = 0; p < 2; p++) {
        if (p) __syncthreads();
        #pragma unroll
        for (int j = 0; j < 4; j++) {        // A: 128x64 fp32 -> fp16
            int i = tid + j * 256;
            int row = i >> 3, c8 = (i & 7) * 8;
            *(int4*)&As[row][c8] =
                cvt8(X + (mt * 128 + row) * 128 + p * 64 + c8);
        }
        #pragma unroll
        for (int j = 0; j < 2; j++) {        // B: 64x64 fp32 -> fp16
            int i = tid + j * 256;
            int row = i >> 3, c8 = (i & 7) * 8;
            *(int4*)&Bs[row][c8] =
                cvt8(Wq + (p * 64 + row) * 384 + nc * 64 + c8);
        }
        __syncthreads();

        #pragma unroll
        for (int kc = 0; kc < 4; kc++) {
            unsigned a[4];
            LDMX4(a[0], a[1], a[2], a[3], as_base +
                (uint32_t)(((warp * 16 + (lane & 15)) * GP + kc * 16 + (lane >> 4) * 8) * 2));
            #pragma unroll
            for (int t = 0; t < 4; t++) {
                unsigned b0, b1, b2, b3;
                LDMX4T(b0, b1, b2, b3, bs_base +
                    (uint32_t)(((kc * 16 + (lane & 15)) * GP + t * 16 + (lane >> 4) * 8) * 2));
                MMA16816(acc[2 * t],     a, b0, b1);
                MMA16816(acc[2 * t + 1], a, b2, b3);
            }
        }
    }

    // epilogue: all fp16
    #pragma unroll
    for (int t = 0; t < 8; t++) {
        int e  = nc * 64 + t * 8 + q2;
        int ec = e & 127;
        int h  = ec >> 5, d = ec & 31;
        #pragma unroll
        for (int half_ = 0; half_ < 2; half_++) {
            int m = mt * 128 + warp * 16 + g + half_ * 8;
            int b = m >> 12, n = m & 4095;
            int idx = ((b * 4 + h) * 4096 + n) * 32 + d;
            __half2 hv = __float22half2_rn(
                make_float2(acc[t][half_ * 2], acc[t][half_ * 2 + 1]));
            if (nc < 2)      *(__half2*)&g_Qh[idx] = hv;
            else if (nc < 4) *(__half2*)&g_Kh[idx] = hv;
            else             *(__half2*)&g_Vh[idx] = hv;
        }
    }
}

// =====================================================================
// Kernel 2: column sum-of-squares partials (fp16 src, fp32 acc).
// grid 256 = 16 bh x {q,k} x 8 chunks of 512 rows. Deterministic.
// =====================================================================
__global__ __launch_bounds__(256) void colnorm_partial()
{
    const int bx = blockIdx.x;
    const int bh = bx & 15;
    const int r  = bx >> 4;
    const int which = r & 1;          // 0 = q, 1 = k
    const int chunk = r >> 1;         // 0..7
    const __half* src = (which ? g_Kh : g_Qh) + (bh * N_ + chunk * 512) * 32;
    const int d = threadIdx.x & 31;
    const int grp = threadIdx.x >> 5;

    float s = 0.f;
    for (int n = grp; n < 512; n += 8) {
        float v = __half2float(src[n * 32 + d]);
        s = fmaf(v, v, s);
    }
    __shared__ float red[256];
    red[threadIdx.x] = s;
    __syncthreads();
    if (threadIdx.x < 32) {
        float tot = 0.f;
        #pragma unroll
        for (int g = 0; g < 8; g++) tot += red[g * 32 + d];
        g_part[which][chunk][bh * 32 + d] = tot;
    }
}

// =====================================================================
// Kernel 3: flash attention. Scale computed in-block from g_part,
// applied at Q staging; exp via ex2.approx.f16x2; row-sum l via
// fp16 pair-sum tree + fp32 accumulation (tensor pipe relieved);
// 1 barrier/iter. grid (32 q-tiles of 128, 16 bh), 256 thr.
// =====================================================================
#define PITCH     40                    // halves per smem row
#define KV_BYTES  (64 * PITCH * 2)      // bytes per K or V stage

__global__ __launch_bounds__(256) void flash_kernel()
{
    const int qt   = blockIdx.x;      // 0..31
    const int bh   = blockIdx.y;      // 0..15
    const int tid  = threadIdx.x;
    const int lane = tid & 31;
    const int warp = tid >> 5;        // 0..7
    const int g    = lane >> 2;       // 0..7

    __shared__ __align__(16) __half Qs[128][PITCH];
    __shared__ __align__(16) __half Ks[2][64][PITCH];
    __shared__ __align__(16) __half Vs[2][64][PITCH];
    __shared__ float scl[32];

    const __half* Qg = g_Qh + (bh * N_ + qt * 128) * 32;
    const __half* Kg = g_Kh + bh * N_ * 32;
    const __half* Vg = g_Vh + bh * N_ * 32;

    const uint32_t qs_base = (uint32_t)__cvta_generic_to_shared(&Qs[0][0]);
    const uint32_t ks_base = (uint32_t)__cvta_generic_to_shared(&Ks[0][0][0]);
    const uint32_t vs_base = (uint32_t)__cvta_generic_to_shared(&Vs[0][0][0]);

    const int crow = tid >> 2;
    const int ccol = (tid & 3) * 8;
    const uint32_t cdst = (uint32_t)(crow * (PITCH * 2) + ccol * 2);
    const int     csrc  = crow * 32 + ccol;

    // prefetch KV tile 0
    cp16(ks_base + cdst, Kg + csrc);
    cp16(vs_base + cdst, Vg + csrc);
    CP_COMMIT();

    // per-block scale finalize
    if (tid < 32) {
        float qs = 0.f, ks = 0.f;
        #pragma unroll
        for (int c = 0; c < 8; c++) {
            qs += g_part[0][c][bh * 32 + tid];
            ks += g_part[1][c][bh * 32 + tid];
        }
        float qn = fmaxf(sqrtf(qs), 1e-12f);
        float kn = fmaxf(sqrtf(ks), 1e-12f);
        scl[tid] = 14.4269504088896f / (qn * kn);   // 10*log2(e)/(|q||k|)
    }
    __syncthreads();

    // stage Q (raw fp16 * fp32 scale -> fp16) while tile 0 streams
    {
        const int d0 = (tid & 3) * 8;
        float sc[8];
        #pragma unroll
        for (int j = 0; j < 8; j++) sc[j] = scl[d0 + j];
        const int4* src = (const int4*)Qg;
        #pragma unroll
        for (int i = tid; i < 512; i += 256) {
            int4 v = src[i];
            __half2* hp = (__half2*)&v;
            #pragma unroll
            for (int j = 0; j < 4; j++) {
                float2 fv = __half22float2(hp[j]);
                fv.x *= sc[2 * j]; fv.y *= sc[2 * j + 1];
                hp[j] = __float22half2_rn(fv);
            }
            *(int4*)&Qs[i >> 2][(i & 3) * 8] = v;
        }
    }
    __syncthreads();

    // Q A-fragments for the whole loop
    unsigned qa[2][4];
    const int rb = warp * 16;
    #pragma unroll
    for (int kc = 0; kc < 2; kc++) {
        uint32_t addr = qs_base +
            (uint32_t)(((rb + (lane & 15)) * PITCH + kc * 16 + (lane >> 4) * 8) * 2);
        LDMX4(qa[kc][0], qa[kc][1], qa[kc][2], qa[kc][3], addr);
    }

    float o[4][4];
    #pragma unroll
    for (int t = 0; t < 4; t++)
        #pragma unroll
        for (int r = 0; r < 4; r++) o[t][r] = 0.f;
    float l0 = 0.f, l1 = 0.f;     // per-thread fp32 partial row sums

    for (int kb = 0; kb < 64; kb++) {
        const int st = kb & 1;
        CP_WAIT0();
        __syncthreads();

        if (kb + 1 < 64) {     // prefetch next tile, overlaps compute
            uint32_t off = (uint32_t)((st ^ 1) * KV_BYTES) + cdst;
            int s2 = (kb + 1) * 64 * 32 + csrc;
            cp16(ks_base + off, Kg + s2);
            cp16(vs_base + off, Vg + s2);
            CP_COMMIT();
        }

        const uint32_t kbase = ks_base + st * KV_BYTES;
        const uint32_t vbase = vs_base + st * KV_BYTES;

        // ---- S = Q K^T (16 x 64 per warp), log2-domain logits ----
        float s[8][4];
        #pragma unroll
        for (int t = 0; t < 8; t++) {
            unsigned b0, b1, b2, b3;
            uint32_t addr = kbase +
                (uint32_t)(((t * 8 + (lane & 7)) * PITCH + (lane >> 3) * 8) * 2);
            LDMX4(b0, b1, b2, b3, addr);
            s[t][0] = s[t][1] = s[t][2] = s[t][3] = 0.f;
            MMA16816(s[t], qa[0], b0, b1);
            MMA16816(s[t], qa[1], b2, b3);
        }

        // ---- per jc-chunk: pack -> ex2.f16x2 -> PV MMAs; pair-sums
        //      for l collected in fp16, converted to fp32 per iter ----
        __half2 r0p[4], r1p[4];
        #pragma unroll
        for (int jc = 0; jc < 4; jc++) {
            unsigned pu[4];
            pu[0] = ex2h2(pack_h2(s[2*jc][0],   s[2*jc][1]));
            pu[1] = ex2h2(pack_h2(s[2*jc][2],   s[2*jc][3]));
            pu[2] = ex2h2(pack_h2(s[2*jc+1][0], s[2*jc+1][1]));
            pu[3] = ex2h2(pack_h2(s[2*jc+1][2], s[2*jc+1][3]));

            r0p[jc] = __hadd2(u2h2(pu[0]), u2h2(pu[2]));   // row g
            r1p[jc] = __hadd2(u2h2(pu[1]), u2h2(pu[3]));   // row g+8

            uint32_t a0 = vbase +
                (uint32_t)(((jc * 16 + (lane & 15)) * PITCH + (lane >> 4) * 8) * 2);
            unsigned r0, r1, r2, r3;
            LDMX4T(r0, r1, r2, r3, a0);
            MMA16816(o[0], pu, r0, r1);
            MMA16816(o[1], pu, r2, r3);
            LDMX4T(r0, r1, r2, r3, a0 + 32);
            MMA16816(o[2], pu, r0, r1);
            MMA16816(o[3], pu, r2, r3);
        }
        // fp16 tree -> fp32 accumulate (per iteration, error ~1e-5 rel)
        {
            __half2 a = __hadd2(__hadd2(r0p[0], r0p[1]), __hadd2(r0p[2], r0p[3]));
            __half2 b = __hadd2(__hadd2(r1p[0], r1p[1]), __hadd2(r1p[2], r1p[3]));
            float2 fa = __half22float2(a);
            float2 fb = __half22float2(b);
            l0 += fa.x + fa.y;
            l1 += fb.x + fb.y;
        }
    }

    // ---- finalize: quad-reduce l, divide, write ----
    l0 += __shfl_xor_sync(0xffffffffu, l0, 1);
    l0 += __shfl_xor_sync(0xffffffffu, l0, 2);
    l1 += __shfl_xor_sync(0xffffffffu, l1, 1);
    l1 += __shfl_xor_sync(0xffffffffu, l1, 2);

    const int q2 = (lane & 3) * 2;
    float inv0 = 1.0f / l0;
    float inv1 = 1.0f / l1;

    int b = bh >> 2, h = bh & 3;
    int row0 = qt * 128 + rb + g;
    __half* dst0 = g_Oh + (b * N_ + row0) * 128 + h * 32;
    __half* dst1 = dst0 + 8 * 128;
    #pragma unroll
    for (int t = 0; t < 4; t++) {
        int d = t * 8 + q2;
        *(__half2*)&dst0[d] = __float22half2_rn(make_float2(o[t][0] * inv0, o[t][1] * inv0));
        *(__half2*)&dst1[d] = __float22half2_rn(make_float2(o[t][2] * inv1, o[t][3] * inv1));
    }
}

// =====================================================================
// Kernel 4: output projection fp16 tensor-core (Oh[16384,128] @
// Wout[128,128]fp32->fp16 in staging) + bias, fp32 out. Two-phase.
// =====================================================================
__global__ __launch_bounds__(256) void gemm_out_h(
    const float* __restrict__ Wo, const float* __restrict__ bias,
    float* __restrict__ out)
{
    __shared__ __align__(16) __half As[128][GP];
    __shared__ __align__(16) __half Bs[64][GP];
    const int nc  = blockIdx.x;       // 0..1
    const int mt  = blockIdx.y;       // 0..127
    const int tid = threadIdx.x;
    const int lane = tid & 31;
    const int warp = tid >> 5;
    const int g    = lane >> 2;
    const int q2   = (lane & 3) * 2;

    const uint32_t as_base = (uint32_t)__cvta_generic_to_shared(&As[0][0]);
    const uint32_t bs_base = (uint32_t)__cvta_generic_to_shared(&Bs[0][0]);
    const __half* Ap = g_Oh + mt * 128 * 128;

    float acc[8][4];
    #pragma unroll
    for (int t = 0; t < 8; t++)
        #pragma unroll
        for (int r = 0; r < 4; r++) acc[t][r] = 0.f;

    #pragma unroll
    for (int p = 0; p < 2; p++) {
        if (p) __syncthreads();
        #pragma unroll
        for (int j = 0; j < 4; j++) {        // A: fp16 via cp.async
            int i = tid + j * 256;
            int row = i >> 3, c8 = (i & 7) * 8;
            cp16(as_base + (uint32_t)((row * GP + c8) * 2),
                 Ap + row * 128 + p * 64 + c8);
        }
        #pragma unroll
        for (int j = 0; j < 2; j++) {        // B: fp32 -> fp16 in staging
            int i = tid + j * 256;
            int row = i >> 3, c8 = (i & 7) * 8;
            *(int4*)&Bs[row][c8] =
                cvt8(Wo + (p * 64 + row) * 128 + nc * 64 + c8);
        }
        CP_COMMIT(); CP_WAIT0();
        __syncthreads();

        #pragma unroll
        for (int kc = 0; kc < 4; kc++) {
            unsigned a[4];
            LDMX4(a[0], a[1], a[2], a[3], as_base +
                (uint32_t)(((warp * 16 + (lane & 15)) * GP + kc * 16 + (lane >> 4) * 8) * 2));
            #pragma unroll
            for (int t = 0; t < 4; t++) {
                unsigned b0, b1, b2, b3;
                LDMX4T(b0, b1, b2, b3, bs_base +
                    (uint32_t)(((kc * 16 + (lane & 15)) * GP + t * 16 + (lane >> 4) * 8) * 2));
                MMA16816(acc[2 * t],     a, b0, b1);
                MMA16816(acc[2 * t + 1], a, b2, b3);
            }
        }
    }

    #pragma unroll
    for (int t = 0; t < 8; t++) {
        int e = nc * 64 + t * 8 + q2;
        float2 bv = *(const float2*)&bias[e];
        #pragma unroll
        for (int half_ = 0; half_ < 2; half_++) {
            int m = mt * 128 + warp * 16 + g + half_ * 8;
            *(float2*)&out[m * 128 + e] =
                make_float2(acc[t][half_ * 2] + bv.x, acc[t][half_ * 2 + 1] + bv.y);
        }
    }
}

// =====================================================================
extern "C" void kernel_launch(void* const* d_in, const int* in_sizes, int n_in,
                              void* d_out, int out_size)
{
    const float* x     = (const float*)d_in[0];   // [4,4096,128]
    const float* Wqkv  = (const float*)d_in[1];   // [128,384]
    const float* Wout  = (const float*)d_in[2];   // [128,128]
    const float* bout  = (const float*)d_in[3];   // [128]
    float* out = (float*)d_out;                   // [4,4096,128]

    gemm_qkv_h<<<dim3(6, 128), 256>>>(x, Wqkv);
    colnorm_partial<<<256, 256>>>();
    flash_kernel<<<dim3(32, 16), 256>>>();
    gemm_out_h<<<dim3(2, 128), 256>>>(Wout, bout, out);
}

// round 13
// speedup vs baseline: 1.2069x; 1.0166x over previous
#include <cuda_runtime.h>
#include <cuda_fp16.h>
#include <cstdint>

// Problem constants
#define B_   4
#define N_   4096
#define C_   128
#define H_   4
#define D_   32
#define BH_  (B_*H_)           // 16
#define QK_ELEMS (BH_*N_*D_)   // 2,097,152

// ---------------- static scratch (no allocs allowed) ----------------
__device__ __half g_Qh[QK_ELEMS];        // raw q (unnormalized) fp16
__device__ __half g_Kh[QK_ELEMS];        // raw k fp16
__device__ __half g_Vh[QK_ELEMS];
__device__ __half g_Oh[B_*N_*C_];        // attention output fp16 [b][n][h*32+d]
__device__ float  g_part[2][32][512];    // column sumsq partials [q/k][128-row chunk][bh*32+d]

// ---------------- PTX helpers ----------------
#define MMA16816(d, a, b0, b1)                                                  \
    asm volatile("mma.sync.aligned.m16n8k16.row.col.f32.f16.f16.f32 "          \
        "{%0,%1,%2,%3}, {%4,%5,%6,%7}, {%8,%9}, {%0,%1,%2,%3};\n"              \
        : "+f"(d[0]), "+f"(d[1]), "+f"(d[2]), "+f"(d[3])                        \
        : "r"(a[0]), "r"(a[1]), "r"(a[2]), "r"(a[3]), "r"(b0), "r"(b1))

#define LDMX4(r0,r1,r2,r3,addr)                                                 \
    asm volatile("ldmatrix.sync.aligned.m8n8.x4.shared.b16 {%0,%1,%2,%3}, [%4];\n" \
        : "=r"(r0), "=r"(r1), "=r"(r2), "=r"(r3) : "r"(addr))

#define LDMX4T(r0,r1,r2,r3,addr)                                                \
    asm volatile("ldmatrix.sync.aligned.m8n8.x4.trans.shared.b16 {%0,%1,%2,%3}, [%4];\n" \
        : "=r"(r0), "=r"(r1), "=r"(r2), "=r"(r3) : "r"(addr))

__device__ __forceinline__ void cp16(uint32_t dst, const void* src) {
    asm volatile("cp.async.cg.shared.global [%0], [%1], 16;\n" :: "r"(dst), "l"(src));
}
#define CP_COMMIT() asm volatile("cp.async.commit_group;\n" ::: "memory")
#define CP_WAIT0()  asm volatile("cp.async.wait_group 0;\n" ::: "memory")

__device__ __forceinline__ unsigned pack_h2(float x, float y) {
    __half2 h = __float22half2_rn(make_float2(x, y));
    return *reinterpret_cast<unsigned*>(&h);
}
__device__ __forceinline__ unsigned ex2h2(unsigned x) {
    unsigned r; asm("ex2.approx.f16x2 %0, %1;" : "=r"(r) : "r"(x)); return r;
}
__device__ __forceinline__ __half2 u2h2(unsigned x) {
    return *reinterpret_cast<__half2*>(&x);
}

// convert 8 consecutive fp32 -> int4 of 8 halves
__device__ __forceinline__ int4 cvt8(const float* __restrict__ src) {
    float4 v0 = *(const float4*)src;
    float4 v1 = *(const float4*)(src + 4);
    __half2 h[4];
    h[0] = __float22half2_rn(make_float2(v0.x, v0.y));
    h[1] = __float22half2_rn(make_float2(v0.z, v0.w));
    h[2] = __float22half2_rn(make_float2(v1.x, v1.y));
    h[3] = __float22half2_rn(make_float2(v1.z, v1.w));
    return *(int4*)h;
}

// =====================================================================
// Kernel 1: QKV GEMM fp16 tensor-core, fp32 inputs converted in-staging,
// FUSED per-column sumsq partials for q/k (replaces colnorm kernel).
// grid (6 nc of 64, 128 mt of 128), 256 thr.
// =====================================================================
#define GP 72   // smem pitch in halves

__global__ __launch_bounds__(256) void gemm_qkv_h(
    const float* __restrict__ X, const float* __restrict__ Wq)
{
    __shared__ __align__(16) __half As[128][GP];
    __shared__ __align__(16) __half Bs[64][GP];
    __shared__ float wsum[8][64];

    const int nc  = blockIdx.x;       // 0..5
    const int mt  = blockIdx.y;       // 0..127
    const int tid = threadIdx.x;
    const int lane = tid & 31;
    const int warp = tid >> 5;
    const int g    = lane >> 2;
    const int q2   = (lane & 3) * 2;

    const uint32_t as_base = (uint32_t)__cvta_generic_to_shared(&As[0][0]);
    const uint32_t bs_base = (uint32_t)__cvta_generic_to_shared(&Bs[0][0]);

    float acc[8][4];
    #pragma unroll
    for (int t = 0; t < 8; t++)
        #pragma unroll
        for (int r = 0; r < 4; r++) acc[t][r] = 0.f;

    #pragma unroll
    for (int p = 0; p < 2; p++) {
        if (p) __syncthreads();
        #pragma unroll
        for (int j = 0; j < 4; j++) {        // A: 128x64 fp32 -> fp16
            int i = tid + j * 256;
            int row = i >> 3, c8 = (i & 7) * 8;
            *(int4*)&As[row][c8] =
                cvt8(X + (mt * 128 + row) * 128 + p * 64 + c8);
        }
        #pragma unroll
        for (int j = 0; j < 2; j++) {        // B: 64x64 fp32 -> fp16
            int i = tid + j * 256;
            int row = i >> 3, c8 = (i & 7) * 8;
            *(int4*)&Bs[row][c8] =
                cvt8(Wq + (p * 64 + row) * 384 + nc * 64 + c8);
        }
        __syncthreads();

        #pragma unroll
        for (int kc = 0; kc < 4; kc++) {
            unsigned a[4];
            LDMX4(a[0], a[1], a[2], a[3], as_base +
                (uint32_t)(((warp * 16 + (lane & 15)) * GP + kc * 16 + (lane >> 4) * 8) * 2));
            #pragma unroll
            for (int t = 0; t < 4; t++) {
                unsigned b0, b1, b2, b3;
                LDMX4T(b0, b1, b2, b3, bs_base +
                    (uint32_t)(((kc * 16 + (lane & 15)) * GP + t * 16 + (lane >> 4) * 8) * 2));
                MMA16816(acc[2 * t],     a, b0, b1);
                MMA16816(acc[2 * t + 1], a, b2, b3);
            }
        }
    }

    // epilogue: all fp16 stores
    #pragma unroll
    for (int t = 0; t < 8; t++) {
        int e  = nc * 64 + t * 8 + q2;
        int ec = e & 127;
        int h  = ec >> 5, d = ec & 31;
        #pragma unroll
        for (int half_ = 0; half_ < 2; half_++) {
            int m = mt * 128 + warp * 16 + g + half_ * 8;
            int b = m >> 12, n = m & 4095;
            int idx = ((b * 4 + h) * 4096 + n) * 32 + d;
            __half2 hv = __float22half2_rn(
                make_float2(acc[t][half_ * 2], acc[t][half_ * 2 + 1]));
            if (nc < 2)      *(__half2*)&g_Qh[idx] = hv;
            else if (nc < 4) *(__half2*)&g_Kh[idx] = hv;
            else             *(__half2*)&g_Vh[idx] = hv;
        }
    }

    // fused column sumsq over this block's 128 rows (q/k only).
    // Each warp covers all 64 cols for its 16 rows; shuffle over g
    // sums the 16 rows; wsum then sums the 8 warps. Fixed order.
    if (nc < 4) {
        #pragma unroll
        for (int t = 0; t < 8; t++) {
            float s0 = acc[t][0]*acc[t][0] + acc[t][2]*acc[t][2];
            float s1 = acc[t][1]*acc[t][1] + acc[t][3]*acc[t][3];
            #pragma unroll
            for (int m = 4; m < 32; m <<= 1) {
                s0 += __shfl_xor_sync(0xffffffffu, s0, m);
                s1 += __shfl_xor_sync(0xffffffffu, s1, m);
            }
            if (g == 0) {
                wsum[warp][t * 8 + q2]     = s0;
                wsum[warp][t * 8 + q2 + 1] = s1;
            }
        }
        __syncthreads();
        if (tid < 64) {
            float s = 0.f;
            #pragma unroll
            for (int w = 0; w < 8; w++) s += wsum[w][tid];
            int e  = nc * 64 + tid;
            int which = e >> 7;            // 0=q, 1=k
            int ec = e & 127;
            int h  = ec >> 5, d = ec & 31;
            int b  = mt >> 5;              // batch
            g_part[which][mt & 31][(b * 4 + h) * 32 + d] = s;
        }
    }
}

// =====================================================================
// Kernel 2: flash attention. Scale finalized in-block from g_part by
// ALL 256 threads (parallel gather + 2-level reduce), applied at Q
// staging; exp via ex2.approx.f16x2; row-sum l via fp16 pair-sum tree
// + fp32 accumulation; 1 barrier/iter.
// grid (32 q-tiles of 128, 16 bh), 256 thr.
// =====================================================================
#define PITCH     40                    // halves per smem row
#define KV_BYTES  (64 * PITCH * 2)      // bytes per K or V stage

__global__ __launch_bounds__(256) void flash_kernel()
{
    const int qt   = blockIdx.x;      // 0..31
    const int bh   = blockIdx.y;      // 0..15
    const int tid  = threadIdx.x;
    const int lane = tid & 31;
    const int warp = tid >> 5;        // 0..7
    const int g    = lane >> 2;       // 0..7

    __shared__ __align__(16) __half Qs[128][PITCH];
    __shared__ __align__(16) __half Ks[2][64][PITCH];
    __shared__ __align__(16) __half Vs[2][64][PITCH];
    __shared__ float scl[32];
    __shared__ float red2[16][32];

    const __half* Qg = g_Qh + (bh * N_ + qt * 128) * 32;
    const __half* Kg = g_Kh + bh * N_ * 32;
    const __half* Vg = g_Vh + bh * N_ * 32;

    const uint32_t qs_base = (uint32_t)__cvta_generic_to_shared(&Qs[0][0]);
    const uint32_t ks_base = (uint32_t)__cvta_generic_to_shared(&Ks[0][0][0]);
    const uint32_t vs_base = (uint32_t)__cvta_generic_to_shared(&Vs[0][0][0]);

    const int crow = tid >> 2;
    const int ccol = (tid & 3) * 8;
    const uint32_t cdst = (uint32_t)(crow * (PITCH * 2) + ccol * 2);
    const int     csrc  = crow * 32 + ccol;

    // prefetch KV tile 0
    cp16(ks_base + cdst, Kg + csrc);
    cp16(vs_base + cdst, Vg + csrc);
    CP_COMMIT();

    // scale finalize: 256 threads gather 32 chunks x {q,k} x 32 cols
    {
        int col = tid & 31;
        int grp = tid >> 5;          // 0..7, 4 chunks each
        float qs = 0.f, ks = 0.f;
        #pragma unroll
        for (int c = 0; c < 4; c++) {
            qs += g_part[0][grp * 4 + c][bh * 32 + col];
            ks += g_part[1][grp * 4 + c][bh * 32 + col];
        }
        red2[grp][col]     = qs;
        red2[8 + grp][col] = ks;
    }
    __syncthreads();
    if (tid < 32) {
        float qt_ = 0.f, kt_ = 0.f;
        #pragma unroll
        for (int w = 0; w < 8; w++) {
            qt_ += red2[w][tid];
            kt_ += red2[8 + w][tid];
        }
        float qn = fmaxf(sqrtf(qt_), 1e-12f);
        float kn = fmaxf(sqrtf(kt_), 1e-12f);
        scl[tid] = 14.4269504088896f / (qn * kn);   // 10*log2(e)/(|q||k|)
    }
    __syncthreads();

    // stage Q (raw fp16 * fp32 scale -> fp16) while tile 0 streams
    {
        const int d0 = (tid & 3) * 8;
        float sc[8];
        #pragma unroll
        for (int j = 0; j < 8; j++) sc[j] = scl[d0 + j];
        const int4* src = (const int4*)Qg;
        #pragma unroll
        for (int i = tid; i < 512; i += 256) {
            int4 v = src[i];
            __half2* hp = (__half2*)&v;
            #pragma unroll
            for (int j = 0; j < 4; j++) {
                float2 fv = __half22float2(hp[j]);
                fv.x *= sc[2 * j]; fv.y *= sc[2 * j + 1];
                hp[j] = __float22half2_rn(fv);
            }
            *(int4*)&Qs[i >> 2][(i & 3) * 8] = v;
        }
    }
    __syncthreads();

    // Q A-fragments for the whole loop
    unsigned qa[2][4];
    const int rb = warp * 16;
    #pragma unroll
    for (int kc = 0; kc < 2; kc++) {
        uint32_t addr = qs_base +
            (uint32_t)(((rb + (lane & 15)) * PITCH + kc * 16 + (lane >> 4) * 8) * 2);
        LDMX4(qa[kc][0], qa[kc][1], qa[kc][2], qa[kc][3], addr);
    }

    float o[4][4];
    #pragma unroll
    for (int t = 0; t < 4; t++)
        #pragma unroll
        for (int r = 0; r < 4; r++) o[t][r] = 0.f;
    float l0 = 0.f, l1 = 0.f;     // per-thread fp32 partial row sums

    for (int kb = 0; kb < 64; kb++) {
        const int st = kb & 1;
        CP_WAIT0();
        __syncthreads();

        if (kb + 1 < 64) {     // prefetch next tile, overlaps compute
            uint32_t off = (uint32_t)((st ^ 1) * KV_BYTES) + cdst;
            int s2 = (kb + 1) * 64 * 32 + csrc;
            cp16(ks_base + off, Kg + s2);
            cp16(vs_base + off, Vg + s2);
            CP_COMMIT();
        }

        const uint32_t kbase = ks_base + st * KV_BYTES;
        const uint32_t vbase = vs_base + st * KV_BYTES;

        // ---- S = Q K^T (16 x 64 per warp), log2-domain logits ----
        float s[8][4];
        #pragma unroll
        for (int t = 0; t < 8; t++) {
            unsigned b0, b1, b2, b3;
            uint32_t addr = kbase +
                (uint32_t)(((t * 8 + (lane & 7)) * PITCH + (lane >> 3) * 8) * 2);
            LDMX4(b0, b1, b2, b3, addr);
            s[t][0] = s[t][1] = s[t][2] = s[t][3] = 0.f;
            MMA16816(s[t], qa[0], b0, b1);
            MMA16816(s[t], qa[1], b2, b3);
        }

        // ---- per jc-chunk: pack -> ex2.f16x2 -> PV MMAs; pair-sums
        //      for l collected in fp16, converted to fp32 per iter ----
        __half2 r0p[4], r1p[4];
        #pragma unroll
        for (int jc = 0; jc < 4; jc++) {
            unsigned pu[4];
            pu[0] = ex2h2(pack_h2(s[2*jc][0],   s[2*jc][1]));
            pu[1] = ex2h2(pack_h2(s[2*jc][2],   s[2*jc][3]));
            pu[2] = ex2h2(pack_h2(s[2*jc+1][0], s[2*jc+1][1]));
            pu[3] = ex2h2(pack_h2(s[2*jc+1][2], s[2*jc+1][3]));

            r0p[jc] = __hadd2(u2h2(pu[0]), u2h2(pu[2]));   // row g
            r1p[jc] = __hadd2(u2h2(pu[1]), u2h2(pu[3]));   // row g+8

            uint32_t a0 = vbase +
                (uint32_t)(((jc * 16 + (lane & 15)) * PITCH + (lane >> 4) * 8) * 2);
            unsigned r0, r1, r2, r3;
            LDMX4T(r0, r1, r2, r3, a0);
            MMA16816(o[0], pu, r0, r1);
            MMA16816(o[1], pu, r2, r3);
            LDMX4T(r0, r1, r2, r3, a0 + 32);
            MMA16816(o[2], pu, r0, r1);
            MMA16816(o[3], pu, r2, r3);
        }
        // fp16 tree -> fp32 accumulate (per iteration)
        {
            __half2 a = __hadd2(__hadd2(r0p[0], r0p[1]), __hadd2(r0p[2], r0p[3]));
            __half2 b = __hadd2(__hadd2(r1p[0], r1p[1]), __hadd2(r1p[2], r1p[3]));
            float2 fa = __half22float2(a);
            float2 fb = __half22float2(b);
            l0 += fa.x + fa.y;
            l1 += fb.x + fb.y;
        }
    }

    // ---- finalize: quad-reduce l, divide, write ----
    l0 += __shfl_xor_sync(0xffffffffu, l0, 1);
    l0 += __shfl_xor_sync(0xffffffffu, l0, 2);
    l1 += __shfl_xor_sync(0xffffffffu, l1, 1);
    l1 += __shfl_xor_sync(0xffffffffu, l1, 2);

    const int q2 = (lane & 3) * 2;
    float inv0 = 1.0f / l0;
    float inv1 = 1.0f / l1;

    int b = bh >> 2, h = bh & 3;
    int row0 = qt * 128 + rb + g;
    __half* dst0 = g_Oh + (b * N_ + row0) * 128 + h * 32;
    __half* dst1 = dst0 + 8 * 128;
    #pragma unroll
    for (int t = 0; t < 4; t++) {
        int d = t * 8 + q2;
        *(__half2*)&dst0[d] = __float22half2_rn(make_float2(o[t][0] * inv0, o[t][1] * inv0));
        *(__half2*)&dst1[d] = __float22half2_rn(make_float2(o[t][2] * inv1, o[t][3] * inv1));
    }
}

// =====================================================================
// Kernel 3: output projection fp16 tensor-core (Oh[16384,128] @
// Wout[128,128]fp32->fp16 in staging) + bias, fp32 out. Two-phase.
// =====================================================================
__global__ __launch_bounds__(256) void gemm_out_h(
    const float* __restrict__ Wo, const float* __restrict__ bias,
    float* __restrict__ out)
{
    __shared__ __align__(16) __half As[128][GP];
    __shared__ __align__(16) __half Bs[64][GP];
    const int nc  = blockIdx.x;       // 0..1
    const int mt  = blockIdx.y;       // 0..127
    const int tid = threadIdx.x;
    const int lane = tid & 31;
    const int warp = tid >> 5;
    const int g    = lane >> 2;
    const int q2   = (lane & 3) * 2;

    const uint32_t as_base = (uint32_t)__cvta_generic_to_shared(&As[0][0]);
    const uint32_t bs_base = (uint32_t)__cvta_generic_to_shared(&Bs[0][0]);
    const __half* Ap = g_Oh + mt * 128 * 128;

    float acc[8][4];
    #pragma unroll
    for (int t = 0; t < 8; t++)
        #pragma unroll
        for (int r = 0; r < 4; r++) acc[t][r] = 0.f;

    #pragma unroll
    for (int p = 0; p < 2; p++) {
        if (p) __syncthreads();
        #pragma unroll
        for (int j = 0; j < 4; j++) {        // A: fp16 via cp.async
            int i = tid + j * 256;
            int row = i >> 3, c8 = (i & 7) * 8;
            cp16(as_base + (uint32_t)((row * GP + c8) * 2),
                 Ap + row * 128 + p * 64 + c8);
        }
        #pragma unroll
        for (int j = 0; j < 2; j++) {        // B: fp32 -> fp16 in staging
            int i = tid + j * 256;
            int row = i >> 3, c8 = (i & 7) * 8;
            *(int4*)&Bs[row][c8] =
                cvt8(Wo + (p * 64 + row) * 128 + nc * 64 + c8);
        }
        CP_COMMIT(); CP_WAIT0();
        __syncthreads();

        #pragma unroll
        for (int kc = 0; kc < 4; kc++) {
            unsigned a[4];
            LDMX4(a[0], a[1], a[2], a[3], as_base +
                (uint32_t)(((warp * 16 + (lane & 15)) * GP + kc * 16 + (lane >> 4) * 8) * 2));
            #pragma unroll
            for (int t = 0; t < 4; t++) {
                unsigned b0, b1, b2, b3;
                LDMX4T(b0, b1, b2, b3, bs_base +
                    (uint32_t)(((kc * 16 + (lane & 15)) * GP + t * 16 + (lane >> 4) * 8) * 2));
                MMA16816(acc[2 * t],     a, b0, b1);
                MMA16816(acc[2 * t + 1], a, b2, b3);
            }
        }
    }

    #pragma unroll
    for (int t = 0; t < 8; t++) {
        int e = nc * 64 + t * 8 + q2;
        float2 bv = *(const float2*)&bias[e];
        #pragma unroll
        for (int half_ = 0; half_ < 2; half_++) {
            int m = mt * 128 + warp * 16 + g + half_ * 8;
            *(float2*)&out[m * 128 + e] =
                make_float2(acc[t][half_ * 2] + bv.x, acc[t][half_ * 2 + 1] + bv.y);
        }
    }
}

// =====================================================================
extern "C" void kernel_launch(void* const* d_in, const int* in_sizes, int n_in,
                              void* d_out, int out_size)
{
    const float* x     = (const float*)d_in[0];   // [4,4096,128]
    const float* Wqkv  = (const float*)d_in[1];   // [128,384]
    const float* Wout  = (const float*)d_in[2];   // [128,128]
    const float* bout  = (const float*)d_in[3];   // [128]
    float* out = (float*)d_out;                   // [4,4096,128]

    gemm_qkv_h<<<dim3(6, 128), 256>>>(x, Wqkv);
    flash_kernel<<<dim3(32, 16), 256>>>();
    gemm_out_h<<<dim3(2, 128), 256>>>(Wout, bout, out);
}